// round 5
// baseline (speedup 1.0000x reference)
#include <cuda_runtime.h>
#include <cstdint>

#define BATCH 4
#define SEQ   2048
#define DIM   768
#define NH    12
#define HD    64
#define BH    (BATCH*NH)          // 48
#define MROWS (BATCH*SEQ)         // 8192
#define SCALE 0.125f
#define LOG2E 1.4426950408889634f

// Scratch (allocation-free rule: __device__ globals)
__device__ float g_Q[BH*SEQ*HD];
__device__ float g_K[BH*SEQ*HD];
__device__ float g_V[BH*SEQ*HD];
__device__ float g_AO[BATCH*SEQ*DIM];

__device__ __forceinline__ uint32_t f2tf32(float x) {
    uint32_t r;
    asm("cvt.rna.tf32.f32 %0, %1;" : "=r"(r) : "f"(x));
    return r;
}

__device__ __forceinline__ void mma_tf32(float c[4], uint32_t a0, uint32_t a1,
                                         uint32_t a2, uint32_t a3,
                                         uint32_t b0, uint32_t b1) {
    asm volatile(
        "mma.sync.aligned.m16n8k8.row.col.f32.tf32.tf32.f32 "
        "{%0,%1,%2,%3}, {%4,%5,%6,%7}, {%8,%9}, {%0,%1,%2,%3};"
        : "+f"(c[0]), "+f"(c[1]), "+f"(c[2]), "+f"(c[3])
        : "r"(a0), "r"(a1), "r"(a2), "r"(a3), "r"(b0), "r"(b1));
}

// ---------------------------------------------------------------------------
// mma.sync tf32 NT GEMM, software-pipelined: prefetch chunk c+1 LDG into regs
// while chunk c MMAs run. CTA 128x128, K-chunk 32, 8 warps, warp tile 64x32.
// ---------------------------------------------------------------------------
#define KT    32
#define SSTR  36
#define SM_WORDS (2 * 128 * SSTR)

__global__ __launch_bounds__(256) void gemm_mma(
    const float* __restrict__ Ain, const float* __restrict__ W,
    const float* __restrict__ bias, float* __restrict__ out, int mode)
{
    extern __shared__ uint32_t sm[];
    uint32_t* As = sm;
    uint32_t* Bs = sm + 128 * SSTR;

    const float* A = Ain ? Ain : g_AO;
    int tid  = threadIdx.x;
    int w    = tid >> 5, lane = tid & 31;
    int gr   = lane >> 2, qc = lane & 3;
    int wm   = (w & 1) * 64;
    int wn   = (w >> 1) * 32;
    int bm   = blockIdx.x * 128;
    int bn   = blockIdx.y * 128;

    // Staging addresses are loop-invariant.
    const float* ag[4]; const float* wg[4];
    uint32_t* as_[4]; uint32_t* bs_[4];
    #pragma unroll
    for (int i = 0; i < 4; ++i) {
        int e   = tid + i * 256;
        int row = e >> 3;
        int ks4 = (e & 7) * 4;
        ag[i] = A + (size_t)(bm + row) * DIM + ks4;
        wg[i] = W + (size_t)(bn + row) * DIM + ks4;
        as_[i] = As + row * SSTR + ks4;
        bs_[i] = Bs + row * SSTR + ks4;
    }

    float acc[4][4][4];
    #pragma unroll
    for (int mt = 0; mt < 4; ++mt)
        #pragma unroll
        for (int nt = 0; nt < 4; ++nt)
            #pragma unroll
            for (int i = 0; i < 4; ++i) acc[mt][nt][i] = 0.f;

    float4 pa[4], pw[4];
    #pragma unroll
    for (int i = 0; i < 4; ++i) { pa[i] = *(const float4*)ag[i];
                                  pw[i] = *(const float4*)wg[i]; }

    for (int kc = 0; kc < DIM; kc += KT) {
        #pragma unroll
        for (int i = 0; i < 4; ++i) {
            as_[i][0] = f2tf32(pa[i].x); as_[i][1] = f2tf32(pa[i].y);
            as_[i][2] = f2tf32(pa[i].z); as_[i][3] = f2tf32(pa[i].w);
            bs_[i][0] = f2tf32(pw[i].x); bs_[i][1] = f2tf32(pw[i].y);
            bs_[i][2] = f2tf32(pw[i].z); bs_[i][3] = f2tf32(pw[i].w);
        }
        __syncthreads();
        if (kc + KT < DIM) {
            #pragma unroll
            for (int i = 0; i < 4; ++i) {
                pa[i] = *(const float4*)(ag[i] + kc + KT);
                pw[i] = *(const float4*)(wg[i] + kc + KT);
            }
        }

        #pragma unroll
        for (int ks = 0; ks < KT / 8; ++ks) {
            int k0 = ks * 8;
            uint32_t af[4][4], bf[4][2];
            #pragma unroll
            for (int mt = 0; mt < 4; ++mt) {
                const uint32_t* p = As + (wm + mt * 16 + gr) * SSTR + k0 + qc;
                af[mt][0] = p[0];
                af[mt][1] = p[8 * SSTR];
                af[mt][2] = p[4];
                af[mt][3] = p[8 * SSTR + 4];
            }
            #pragma unroll
            for (int nt = 0; nt < 4; ++nt) {
                const uint32_t* p = Bs + (wn + nt * 8 + gr) * SSTR + k0 + qc;
                bf[nt][0] = p[0];
                bf[nt][1] = p[4];
            }
            #pragma unroll
            for (int mt = 0; mt < 4; ++mt)
                #pragma unroll
                for (int nt = 0; nt < 4; ++nt)
                    mma_tf32(acc[mt][nt], af[mt][0], af[mt][1], af[mt][2],
                             af[mt][3], bf[nt][0], bf[nt][1]);
        }
        __syncthreads();
    }

    int scol = bn + wn;
    if (mode == 0) {
        int s   = scol / DIM;
        int rem = scol % DIM;
        int h   = rem / HD;
        int d0  = rem % HD;
        float* dst = (s == 0) ? g_Q : (s == 1) ? g_K : g_V;
        #pragma unroll
        for (int mt = 0; mt < 4; ++mt) {
            int r0 = bm + wm + mt * 16 + gr;
            int b  = r0 >> 11, n = r0 & (SEQ - 1);
            float* base = dst + ((size_t)(b * NH + h) * SEQ + n) * HD;
            #pragma unroll
            for (int nt = 0; nt < 4; ++nt) {
                int d = d0 + nt * 8 + 2 * qc;
                *(float2*)(base + d) = make_float2(acc[mt][nt][0], acc[mt][nt][1]);
                *(float2*)(base + 8 * HD + d) = make_float2(acc[mt][nt][2], acc[mt][nt][3]);
            }
        }
    } else {
        #pragma unroll
        for (int mt = 0; mt < 4; ++mt) {
            int r0 = bm + wm + mt * 16 + gr;
            float* base = out + (size_t)r0 * DIM;
            #pragma unroll
            for (int nt = 0; nt < 4; ++nt) {
                int cb = scol + nt * 8 + 2 * qc;
                float2 bv = *(const float2*)(bias + cb);
                *(float2*)(base + cb) =
                    make_float2(acc[mt][nt][0] + bv.x, acc[mt][nt][1] + bv.y);
                *(float2*)(base + 8 * DIM + cb) =
                    make_float2(acc[mt][nt][2] + bv.x, acc[mt][nt][3] + bv.y);
            }
        }
    }
}

// ---------------------------------------------------------------------------
// Flash attention, mma.sync tf32, software-pipelined K/V staging.
// Softmax in log2 domain (Q pre-scaled by SCALE*log2e, exp2f everywhere).
// ---------------------------------------------------------------------------
#define ABR 128
#define ABC 64
#define PSTR 68
#define ATT_SMEM ((64 + 64 + 128) * PSTR * 4)   // 69632 bytes

__global__ __launch_bounds__(256) void attn_mma()
{
    extern __shared__ float sh[];
    float* Ks = sh;                  // [64][PSTR]
    float* Vs = sh + 64 * PSTR;      // [64][PSTR]  (V transposed: [dim][key])
    float* Ps = sh + 128 * PSTR;     // [128][PSTR]

    int bh  = blockIdx.y;
    int q0  = blockIdx.x * ABR;
    int tid = threadIdx.x;
    int w   = tid >> 5, lane = tid & 31;
    int gr  = lane >> 2, qc = lane & 3;
    int wm  = w * 16;

    const float* Qb = g_Q + ((size_t)bh * SEQ + q0) * HD;
    const float* Kb = g_K + (size_t)bh * SEQ * HD;
    const float* Vb = g_V + (size_t)bh * SEQ * HD;

    // Q fragments, pre-scaled by SCALE*log2e, tf32-rounded.
    const float qs = SCALE * LOG2E;
    int r0 = wm + gr;
    uint32_t qf[8][4];
    #pragma unroll
    for (int kt = 0; kt < 8; ++kt) {
        int c = kt * 8 + qc;
        qf[kt][0] = f2tf32(Qb[(size_t)r0 * HD + c] * qs);
        qf[kt][1] = f2tf32(Qb[(size_t)(r0 + 8) * HD + c] * qs);
        qf[kt][2] = f2tf32(Qb[(size_t)r0 * HD + c + 4] * qs);
        qf[kt][3] = f2tf32(Qb[(size_t)(r0 + 8) * HD + c + 4] * qs);
    }

    // Loop-invariant staging addresses.
    const float* kg[4]; float* ksm[4];
    const float* vg[4]; int vkey[4], vd4[4];
    #pragma unroll
    for (int i = 0; i < 4; ++i) {
        int slot = tid + i * 256;
        int key  = slot >> 4;
        int d4   = (slot & 15) * 4;
        kg[i]  = Kb + key * HD + d4;
        ksm[i] = Ks + key * PSTR + d4;
        int vk = slot & 63;
        int vd = (slot >> 6) * 4;
        vg[i]  = Vb + vk * HD + vd;
        vkey[i] = vk; vd4[i] = vd;
    }

    float of[8][4];
    #pragma unroll
    for (int nt = 0; nt < 8; ++nt)
        #pragma unroll
        for (int i = 0; i < 4; ++i) of[nt][i] = 0.f;
    float m0 = -1e30f, m1 = -1e30f, l0 = 0.f, l1 = 0.f;

    float4 pk[4], pv[4];
    #pragma unroll
    for (int i = 0; i < 4; ++i) { pk[i] = *(const float4*)kg[i];
                                  pv[i] = *(const float4*)vg[i]; }

    #pragma unroll 1
    for (int t = 0; t < SEQ / ABC; ++t) {
        // Stage prefetched tile t (convert to tf32).
        #pragma unroll
        for (int i = 0; i < 4; ++i) {
            ksm[i][0] = __uint_as_float(f2tf32(pk[i].x));
            ksm[i][1] = __uint_as_float(f2tf32(pk[i].y));
            ksm[i][2] = __uint_as_float(f2tf32(pk[i].z));
            ksm[i][3] = __uint_as_float(f2tf32(pk[i].w));
            Vs[(vd4[i] + 0) * PSTR + vkey[i]] = __uint_as_float(f2tf32(pv[i].x));
            Vs[(vd4[i] + 1) * PSTR + vkey[i]] = __uint_as_float(f2tf32(pv[i].y));
            Vs[(vd4[i] + 2) * PSTR + vkey[i]] = __uint_as_float(f2tf32(pv[i].z));
            Vs[(vd4[i] + 3) * PSTR + vkey[i]] = __uint_as_float(f2tf32(pv[i].w));
        }
        __syncthreads();

        // Prefetch tile t+1 (overlaps with MMAs below).
        if (t + 1 < SEQ / ABC) {
            size_t off = (size_t)(t + 1) * ABC * HD;
            #pragma unroll
            for (int i = 0; i < 4; ++i) {
                pk[i] = *(const float4*)(kg[i] + off);
                pv[i] = *(const float4*)(vg[i] + off);
            }
        }

        // S = Q K^T (scores already in log2 units)
        float sf[8][4];
        #pragma unroll
        for (int nt = 0; nt < 8; ++nt)
            #pragma unroll
            for (int i = 0; i < 4; ++i) sf[nt][i] = 0.f;
        #pragma unroll
        for (int kt = 0; kt < 8; ++kt) {
            int k0 = kt * 8;
            #pragma unroll
            for (int nt = 0; nt < 8; ++nt) {
                const uint32_t* bp =
                    (const uint32_t*)(Ks + (nt * 8 + gr) * PSTR + k0 + qc);
                mma_tf32(sf[nt], qf[kt][0], qf[kt][1], qf[kt][2], qf[kt][3],
                         bp[0], bp[4]);
            }
        }

        // Online softmax (log2 domain)
        float tm0 = -1e30f, tm1 = -1e30f;
        #pragma unroll
        for (int nt = 0; nt < 8; ++nt) {
            tm0 = fmaxf(tm0, fmaxf(sf[nt][0], sf[nt][1]));
            tm1 = fmaxf(tm1, fmaxf(sf[nt][2], sf[nt][3]));
        }
        tm0 = fmaxf(tm0, __shfl_xor_sync(0xffffffffu, tm0, 1));
        tm0 = fmaxf(tm0, __shfl_xor_sync(0xffffffffu, tm0, 2));
        tm1 = fmaxf(tm1, __shfl_xor_sync(0xffffffffu, tm1, 1));
        tm1 = fmaxf(tm1, __shfl_xor_sync(0xffffffffu, tm1, 2));

        float nm0 = fmaxf(m0, tm0), nm1 = fmaxf(m1, tm1);
        float c0 = exp2f(m0 - nm0), c1 = exp2f(m1 - nm1);
        m0 = nm0; m1 = nm1;

        float rs0 = 0.f, rs1 = 0.f;
        float* prow0 = Ps + (wm + gr) * PSTR + 2 * qc;
        float* prow1 = prow0 + 8 * PSTR;
        #pragma unroll
        for (int nt = 0; nt < 8; ++nt) {
            // Round p to tf32 BEFORE accumulating l so num/denom bias cancels.
            float p0 = __uint_as_float(f2tf32(exp2f(sf[nt][0] - nm0)));
            float p1 = __uint_as_float(f2tf32(exp2f(sf[nt][1] - nm0)));
            float p2 = __uint_as_float(f2tf32(exp2f(sf[nt][2] - nm1)));
            float p3 = __uint_as_float(f2tf32(exp2f(sf[nt][3] - nm1)));
            rs0 += p0 + p1;
            rs1 += p2 + p3;
            *(float2*)(prow0 + nt * 8) = make_float2(p0, p1);
            *(float2*)(prow1 + nt * 8) = make_float2(p2, p3);
        }
        rs0 += __shfl_xor_sync(0xffffffffu, rs0, 1);
        rs0 += __shfl_xor_sync(0xffffffffu, rs0, 2);
        rs1 += __shfl_xor_sync(0xffffffffu, rs1, 1);
        rs1 += __shfl_xor_sync(0xffffffffu, rs1, 2);
        l0 = l0 * c0 + rs0;
        l1 = l1 * c1 + rs1;

        #pragma unroll
        for (int nt = 0; nt < 8; ++nt) {
            of[nt][0] *= c0; of[nt][1] *= c0;
            of[nt][2] *= c1; of[nt][3] *= c1;
        }
        __syncwarp();   // P is warp-private; warp-level visibility suffices

        // O += P V
        #pragma unroll
        for (int kt = 0; kt < 8; ++kt) {
            int k0 = kt * 8;
            const uint32_t* ap =
                (const uint32_t*)(Ps + (wm + gr) * PSTR + k0 + qc);
            uint32_t a0 = ap[0];
            uint32_t a1 = ap[8 * PSTR];
            uint32_t a2 = ap[4];
            uint32_t a3 = ap[8 * PSTR + 4];
            #pragma unroll
            for (int nt = 0; nt < 8; ++nt) {
                const uint32_t* bp =
                    (const uint32_t*)(Vs + (nt * 8 + gr) * PSTR + k0 + qc);
                mma_tf32(of[nt], a0, a1, a2, a3, bp[0], bp[4]);
            }
        }
        __syncthreads();
    }

    // Epilogue
    float inv0 = 1.f / l0, inv1 = 1.f / l1;
    int b = bh / NH, h = bh % NH;
    int n0 = q0 + wm + gr;
    float* o0 = g_AO + ((size_t)(b * SEQ + n0)) * DIM + h * HD;
    float* o1 = g_AO + ((size_t)(b * SEQ + n0 + 8)) * DIM + h * HD;
    #pragma unroll
    for (int nt = 0; nt < 8; ++nt) {
        int d = nt * 8 + 2 * qc;
        *(float2*)(o0 + d) = make_float2(of[nt][0] * inv0, of[nt][1] * inv0);
        *(float2*)(o1 + d) = make_float2(of[nt][2] * inv1, of[nt][3] * inv1);
    }
}

// ---------------------------------------------------------------------------
extern "C" void kernel_launch(void* const* d_in, const int* in_sizes, int n_in,
                              void* d_out, int out_size)
{
    const float* x      = (const float*)d_in[0];
    const float* w_qkv  = (const float*)d_in[1];
    const float* w_proj = (const float*)d_in[2];
    const float* b_proj = (const float*)d_in[3];
    float* out = (float*)d_out;

    cudaFuncSetAttribute(attn_mma, cudaFuncAttributeMaxDynamicSharedMemorySize,
                         ATT_SMEM);

    size_t smem = SM_WORDS * sizeof(uint32_t);  // 36 KB
    gemm_mma<<<dim3(MROWS/128, 3*DIM/128), 256, smem>>>(x, w_qkv, nullptr, nullptr, 0);
    attn_mma<<<dim3(SEQ/ABR, BH), 256, ATT_SMEM>>>();
    gemm_mma<<<dim3(MROWS/128, DIM/128), 256, smem>>>(nullptr, w_proj, b_proj, out, 1);
}

// round 6
// speedup vs baseline: 1.1441x; 1.1441x over previous
#include <cuda_runtime.h>
#include <cstdint>

#define BATCH 4
#define SEQ   2048
#define DIM   768
#define NH    12
#define HD    64
#define BH    (BATCH*NH)          // 48
#define MROWS (BATCH*SEQ)         // 8192
#define SCALE 0.125f
#define LOG2E 1.4426950408889634f

// Scratch (allocation-free rule: __device__ globals)
__device__ float g_Q[BH*SEQ*HD];
__device__ float g_K[BH*SEQ*HD];
__device__ float g_V[BH*SEQ*HD];
__device__ float g_AO[BATCH*SEQ*DIM];

__device__ __forceinline__ uint32_t f2tf32(float x) {
    uint32_t r;
    asm("cvt.rna.tf32.f32 %0, %1;" : "=r"(r) : "f"(x));
    return r;
}

__device__ __forceinline__ float ex2(float x) {   // single MUFU.EX2
    float r;
    asm("ex2.approx.ftz.f32 %0, %1;" : "=f"(r) : "f"(x));
    return r;
}

__device__ __forceinline__ void mma_tf32(float c[4], uint32_t a0, uint32_t a1,
                                         uint32_t a2, uint32_t a3,
                                         uint32_t b0, uint32_t b1) {
    asm volatile(
        "mma.sync.aligned.m16n8k8.row.col.f32.tf32.tf32.f32 "
        "{%0,%1,%2,%3}, {%4,%5,%6,%7}, {%8,%9}, {%0,%1,%2,%3};"
        : "+f"(c[0]), "+f"(c[1]), "+f"(c[2]), "+f"(c[3])
        : "r"(a0), "r"(a1), "r"(a2), "r"(a3), "r"(b0), "r"(b1));
}

// ---------------------------------------------------------------------------
// mma.sync tf32 NT GEMM (R4-validated structure, no register prefetch)
// ---------------------------------------------------------------------------
#define KT    32
#define SSTR  36
#define SM_WORDS (2 * 128 * SSTR)

__global__ __launch_bounds__(256) void gemm_mma(
    const float* __restrict__ Ain, const float* __restrict__ W,
    const float* __restrict__ bias, float* __restrict__ out, int mode)
{
    extern __shared__ uint32_t sm[];
    uint32_t* As = sm;
    uint32_t* Bs = sm + 128 * SSTR;

    const float* A = Ain ? Ain : g_AO;
    int tid  = threadIdx.x;
    int w    = tid >> 5, lane = tid & 31;
    int gr   = lane >> 2, qc = lane & 3;
    int wm   = (w & 1) * 64;
    int wn   = (w >> 1) * 32;
    int bm   = blockIdx.x * 128;
    int bn   = blockIdx.y * 128;

    float acc[4][4][4];
    #pragma unroll
    for (int mt = 0; mt < 4; ++mt)
        #pragma unroll
        for (int nt = 0; nt < 4; ++nt)
            #pragma unroll
            for (int i = 0; i < 4; ++i) acc[mt][nt][i] = 0.f;

    for (int kc = 0; kc < DIM; kc += KT) {
        #pragma unroll
        for (int i = 0; i < 4; ++i) {
            int e   = tid + i * 256;
            int row = e >> 3;
            int ks4 = (e & 7) * 4;
            float4 av = *(const float4*)(A + (size_t)(bm + row) * DIM + kc + ks4);
            float4 wv = *(const float4*)(W + (size_t)(bn + row) * DIM + kc + ks4);
            uint32_t* ap = As + row * SSTR + ks4;
            uint32_t* bp = Bs + row * SSTR + ks4;
            ap[0] = f2tf32(av.x); ap[1] = f2tf32(av.y);
            ap[2] = f2tf32(av.z); ap[3] = f2tf32(av.w);
            bp[0] = f2tf32(wv.x); bp[1] = f2tf32(wv.y);
            bp[2] = f2tf32(wv.z); bp[3] = f2tf32(wv.w);
        }
        __syncthreads();

        #pragma unroll
        for (int ks = 0; ks < KT / 8; ++ks) {
            int k0 = ks * 8;
            uint32_t af[4][4], bf[4][2];
            #pragma unroll
            for (int mt = 0; mt < 4; ++mt) {
                const uint32_t* p = As + (wm + mt * 16 + gr) * SSTR + k0 + qc;
                af[mt][0] = p[0];
                af[mt][1] = p[8 * SSTR];
                af[mt][2] = p[4];
                af[mt][3] = p[8 * SSTR + 4];
            }
            #pragma unroll
            for (int nt = 0; nt < 4; ++nt) {
                const uint32_t* p = Bs + (wn + nt * 8 + gr) * SSTR + k0 + qc;
                bf[nt][0] = p[0];
                bf[nt][1] = p[4];
            }
            #pragma unroll
            for (int mt = 0; mt < 4; ++mt)
                #pragma unroll
                for (int nt = 0; nt < 4; ++nt)
                    mma_tf32(acc[mt][nt], af[mt][0], af[mt][1], af[mt][2],
                             af[mt][3], bf[nt][0], bf[nt][1]);
        }
        __syncthreads();
    }

    int scol = bn + wn;
    if (mode == 0) {
        int s   = scol / DIM;
        int rem = scol % DIM;
        int h   = rem / HD;
        int d0  = rem % HD;
        float* dst = (s == 0) ? g_Q : (s == 1) ? g_K : g_V;
        #pragma unroll
        for (int mt = 0; mt < 4; ++mt) {
            int r0 = bm + wm + mt * 16 + gr;
            int b  = r0 >> 11, n = r0 & (SEQ - 1);
            float* base = dst + ((size_t)(b * NH + h) * SEQ + n) * HD;
            #pragma unroll
            for (int nt = 0; nt < 4; ++nt) {
                int d = d0 + nt * 8 + 2 * qc;
                *(float2*)(base + d) = make_float2(acc[mt][nt][0], acc[mt][nt][1]);
                *(float2*)(base + 8 * HD + d) = make_float2(acc[mt][nt][2], acc[mt][nt][3]);
            }
        }
    } else {
        #pragma unroll
        for (int mt = 0; mt < 4; ++mt) {
            int r0 = bm + wm + mt * 16 + gr;
            float* base = out + (size_t)r0 * DIM;
            #pragma unroll
            for (int nt = 0; nt < 4; ++nt) {
                int cb = scol + nt * 8 + 2 * qc;
                float2 bv = *(const float2*)(bias + cb);
                *(float2*)(base + cb) =
                    make_float2(acc[mt][nt][0] + bv.x, acc[mt][nt][1] + bv.y);
                *(float2*)(base + 8 * DIM + cb) =
                    make_float2(acc[mt][nt][2] + bv.x, acc[mt][nt][3] + bv.y);
            }
        }
    }
}

// ---------------------------------------------------------------------------
// Flash attention, mma.sync tf32 (R4 staging structure).
// Softmax in log2 domain: Q pre-scaled by SCALE*log2e, hardware ex2.approx.
// ---------------------------------------------------------------------------
#define ABR 128
#define ABC 64
#define PSTR 68
#define ATT_SMEM ((64 + 64 + 128) * PSTR * 4)   // 69632 bytes

__global__ __launch_bounds__(256) void attn_mma()
{
    extern __shared__ float sh[];
    float* Ks = sh;                  // [64][PSTR]
    float* Vs = sh + 64 * PSTR;      // [64][PSTR]  (V transposed: [dim][key])
    float* Ps = sh + 128 * PSTR;     // [128][PSTR]

    int bh  = blockIdx.y;
    int q0  = blockIdx.x * ABR;
    int tid = threadIdx.x;
    int w   = tid >> 5, lane = tid & 31;
    int gr  = lane >> 2, qc = lane & 3;
    int wm  = w * 16;

    const float* Qb = g_Q + ((size_t)bh * SEQ + q0) * HD;
    const float* Kb = g_K + (size_t)bh * SEQ * HD;
    const float* Vb = g_V + (size_t)bh * SEQ * HD;

    // Q fragments, pre-scaled by SCALE*log2e, tf32-rounded.
    const float qs = SCALE * LOG2E;
    int r0 = wm + gr;
    uint32_t qf[8][4];
    #pragma unroll
    for (int kt = 0; kt < 8; ++kt) {
        int c = kt * 8 + qc;
        qf[kt][0] = f2tf32(Qb[(size_t)r0 * HD + c] * qs);
        qf[kt][1] = f2tf32(Qb[(size_t)(r0 + 8) * HD + c] * qs);
        qf[kt][2] = f2tf32(Qb[(size_t)r0 * HD + c + 4] * qs);
        qf[kt][3] = f2tf32(Qb[(size_t)(r0 + 8) * HD + c + 4] * qs);
    }

    float of[8][4];
    #pragma unroll
    for (int nt = 0; nt < 8; ++nt)
        #pragma unroll
        for (int i = 0; i < 4; ++i) of[nt][i] = 0.f;
    float m0 = -1e30f, m1 = -1e30f, l0 = 0.f, l1 = 0.f;

    #pragma unroll 1
    for (int t = 0; t < SEQ / ABC; ++t) {
        const float* Kt = Kb + (size_t)t * ABC * HD;
        const float* Vt = Vb + (size_t)t * ABC * HD;

        // Stage K natural [key][dim]; stage V transposed [dim][key].
        #pragma unroll
        for (int i = 0; i < 4; ++i) {
            int slot = tid + i * 256;
            int key  = slot >> 4;
            int d4   = (slot & 15) * 4;
            float4 kv = *(const float4*)(Kt + key * HD + d4);
            float* p = Ks + key * PSTR + d4;
            p[0] = __uint_as_float(f2tf32(kv.x));
            p[1] = __uint_as_float(f2tf32(kv.y));
            p[2] = __uint_as_float(f2tf32(kv.z));
            p[3] = __uint_as_float(f2tf32(kv.w));
        }
        #pragma unroll
        for (int i = 0; i < 4; ++i) {
            int slot = tid + i * 256;
            int key  = slot & 63;
            int d4   = (slot >> 6) * 4;
            float4 vv = *(const float4*)(Vt + key * HD + d4);
            Vs[(d4 + 0) * PSTR + key] = __uint_as_float(f2tf32(vv.x));
            Vs[(d4 + 1) * PSTR + key] = __uint_as_float(f2tf32(vv.y));
            Vs[(d4 + 2) * PSTR + key] = __uint_as_float(f2tf32(vv.z));
            Vs[(d4 + 3) * PSTR + key] = __uint_as_float(f2tf32(vv.w));
        }
        __syncthreads();

        // S = Q K^T  (scores already in log2 units)
        float sf[8][4];
        #pragma unroll
        for (int nt = 0; nt < 8; ++nt)
            #pragma unroll
            for (int i = 0; i < 4; ++i) sf[nt][i] = 0.f;
        #pragma unroll
        for (int kt = 0; kt < 8; ++kt) {
            int k0 = kt * 8;
            #pragma unroll
            for (int nt = 0; nt < 8; ++nt) {
                const uint32_t* bp =
                    (const uint32_t*)(Ks + (nt * 8 + gr) * PSTR + k0 + qc);
                mma_tf32(sf[nt], qf[kt][0], qf[kt][1], qf[kt][2], qf[kt][3],
                         bp[0], bp[4]);
            }
        }

        // Online softmax (log2 domain, hardware ex2)
        float tm0 = -1e30f, tm1 = -1e30f;
        #pragma unroll
        for (int nt = 0; nt < 8; ++nt) {
            tm0 = fmaxf(tm0, fmaxf(sf[nt][0], sf[nt][1]));
            tm1 = fmaxf(tm1, fmaxf(sf[nt][2], sf[nt][3]));
        }
        tm0 = fmaxf(tm0, __shfl_xor_sync(0xffffffffu, tm0, 1));
        tm0 = fmaxf(tm0, __shfl_xor_sync(0xffffffffu, tm0, 2));
        tm1 = fmaxf(tm1, __shfl_xor_sync(0xffffffffu, tm1, 1));
        tm1 = fmaxf(tm1, __shfl_xor_sync(0xffffffffu, tm1, 2));

        float nm0 = fmaxf(m0, tm0), nm1 = fmaxf(m1, tm1);
        float c0 = ex2(m0 - nm0), c1 = ex2(m1 - nm1);
        m0 = nm0; m1 = nm1;

        float rs0 = 0.f, rs1 = 0.f;
        float* prow0 = Ps + (wm + gr) * PSTR + 2 * qc;
        float* prow1 = prow0 + 8 * PSTR;
        #pragma unroll
        for (int nt = 0; nt < 8; ++nt) {
            // Round p to tf32 BEFORE accumulating l so num/denom bias cancels.
            float p0 = __uint_as_float(f2tf32(ex2(sf[nt][0] - nm0)));
            float p1 = __uint_as_float(f2tf32(ex2(sf[nt][1] - nm0)));
            float p2 = __uint_as_float(f2tf32(ex2(sf[nt][2] - nm1)));
            float p3 = __uint_as_float(f2tf32(ex2(sf[nt][3] - nm1)));
            rs0 += p0 + p1;
            rs1 += p2 + p3;
            *(float2*)(prow0 + nt * 8) = make_float2(p0, p1);
            *(float2*)(prow1 + nt * 8) = make_float2(p2, p3);
        }
        rs0 += __shfl_xor_sync(0xffffffffu, rs0, 1);
        rs0 += __shfl_xor_sync(0xffffffffu, rs0, 2);
        rs1 += __shfl_xor_sync(0xffffffffu, rs1, 1);
        rs1 += __shfl_xor_sync(0xffffffffu, rs1, 2);
        l0 = l0 * c0 + rs0;
        l1 = l1 * c1 + rs1;

        #pragma unroll
        for (int nt = 0; nt < 8; ++nt) {
            of[nt][0] *= c0; of[nt][1] *= c0;
            of[nt][2] *= c1; of[nt][3] *= c1;
        }
        __syncwarp();   // P is warp-private; warp-level visibility suffices

        // O += P V
        #pragma unroll
        for (int kt = 0; kt < 8; ++kt) {
            int k0 = kt * 8;
            const uint32_t* ap =
                (const uint32_t*)(Ps + (wm + gr) * PSTR + k0 + qc);
            uint32_t a0 = ap[0];
            uint32_t a1 = ap[8 * PSTR];
            uint32_t a2 = ap[4];
            uint32_t a3 = ap[8 * PSTR + 4];
            #pragma unroll
            for (int nt = 0; nt < 8; ++nt) {
                const uint32_t* bp =
                    (const uint32_t*)(Vs + (nt * 8 + gr) * PSTR + k0 + qc);
                mma_tf32(of[nt], a0, a1, a2, a3, bp[0], bp[4]);
            }
        }
        __syncthreads();
    }

    // Epilogue
    float inv0 = 1.f / l0, inv1 = 1.f / l1;
    int b = bh / NH, h = bh % NH;
    int n0 = q0 + wm + gr;
    float* o0 = g_AO + ((size_t)(b * SEQ + n0)) * DIM + h * HD;
    float* o1 = g_AO + ((size_t)(b * SEQ + n0 + 8)) * DIM + h * HD;
    #pragma unroll
    for (int nt = 0; nt < 8; ++nt) {
        int d = nt * 8 + 2 * qc;
        *(float2*)(o0 + d) = make_float2(of[nt][0] * inv0, of[nt][1] * inv0);
        *(float2*)(o1 + d) = make_float2(of[nt][2] * inv1, of[nt][3] * inv1);
    }
}

// ---------------------------------------------------------------------------
extern "C" void kernel_launch(void* const* d_in, const int* in_sizes, int n_in,
                              void* d_out, int out_size)
{
    const float* x      = (const float*)d_in[0];
    const float* w_qkv  = (const float*)d_in[1];
    const float* w_proj = (const float*)d_in[2];
    const float* b_proj = (const float*)d_in[3];
    float* out = (float*)d_out;

    cudaFuncSetAttribute(attn_mma, cudaFuncAttributeMaxDynamicSharedMemorySize,
                         ATT_SMEM);

    size_t smem = SM_WORDS * sizeof(uint32_t);  // 36 KB
    gemm_mma<<<dim3(MROWS/128, 3*DIM/128), 256, smem>>>(x, w_qkv, nullptr, nullptr, 0);
    attn_mma<<<dim3(SEQ/ABR, BH), 256, ATT_SMEM>>>();
    gemm_mma<<<dim3(MROWS/128, DIM/128), 256, smem>>>(nullptr, w_proj, b_proj, out, 1);
}